// round 6
// baseline (speedup 1.0000x reference)
#include <cuda_runtime.h>
#include <cuda_bf16.h>
#include <stdint.h>

#define BATCH   256
#define NWARM   128
#define FEAT    1024
#define HID     2048
#define TSTEPS  128
#define OUT_T   (TSTEPS + 1)
#define LDOUT   (OUT_T * FEAT)

// Scratch: ping-pong hidden state + combined cell bias (allocation-free rule).
// NOTE: large __device__ weight statics crash the container — keep footprint small.
__device__ float g_h[2][BATCH * HID];
__device__ float g_bias_cell[HID];

__global__ void init_kernel(const float* __restrict__ b_ih,
                            const float* __restrict__ b_hh)
{
    int i = blockIdx.x * blockDim.x + threadIdx.x;
    if (i < HID) g_bias_cell[i] = b_ih[i] + b_hh[i];
    if (i < BATCH * HID) g_h[0][i] = 0.0f;
}

// Truncation split: hi = top-16-bits of fp32 (exact: f = hi + lo_exact),
// lo = rn_bf16(f - hi). Packed forms: hi pair via one PRMT, lo pair via one CVT.
__device__ __forceinline__ void split4(float4 v, uint2& H, uint2& L) {
    unsigned bx = __float_as_uint(v.x), by = __float_as_uint(v.y);
    unsigned bz = __float_as_uint(v.z), bw = __float_as_uint(v.w);
    H.x = __byte_perm(bx, by, 0x7632);   // {hi(y),hi(x)} packed bf16x2
    H.y = __byte_perm(bz, bw, 0x7632);
    float lx = v.x - __uint_as_float(bx & 0xFFFF0000u);
    float ly = v.y - __uint_as_float(by & 0xFFFF0000u);
    float lz = v.z - __uint_as_float(bz & 0xFFFF0000u);
    float lw = v.w - __uint_as_float(bw & 0xFFFF0000u);
    __nv_bfloat162 l0 = __floats2bfloat162_rn(lx, ly);
    __nv_bfloat162 l1 = __floats2bfloat162_rn(lz, lw);
    L.x = *(unsigned*)&l0;
    L.y = *(unsigned*)&l1;
}

__device__ __forceinline__ void mma16816(float d[4], const unsigned a[4], const unsigned b[2]) {
    asm volatile(
        "mma.sync.aligned.m16n8k16.row.col.f32.bf16.bf16.f32 "
        "{%0,%1,%2,%3}, {%4,%5,%6,%7}, {%8,%9}, {%0,%1,%2,%3};"
        : "+f"(d[0]), "+f"(d[1]), "+f"(d[2]), "+f"(d[3])
        : "r"(a[0]), "r"(a[1]), "r"(a[2]), "r"(a[3]), "r"(b[0]), "r"(b[1]));
}

// C[m,n] = act( sum_k A[m,k]*W[n,k] + bias[n] ), K split across 2 segments.
// A and W fp32 in gmem, split to bf16 (hi,lo) on the fly.
// D = Ah*Wh + Ah*Wl + Al*Wh  (fp32 accumulate in tensor cores).
// BM=64, BK=32 fixed; 256 threads (8 warps), warp grid 2m x 4n,
// warp tile 32 x (BN/4).
template<int BN, bool RELU>
__global__ __launch_bounds__(256)
void gemm_split(const float* __restrict__ A1, int lda1,
                const float* __restrict__ W1, int K1,
                const float* __restrict__ A2, int lda2,
                const float* __restrict__ W2, int K2,
                const float* __restrict__ bias,
                float* __restrict__ C, int ldc)
{
    constexpr int BM = 64, PK = 40;      // PK: 80B pitch -> conflict-free frags
    constexpr int WNJ = BN / 32;         // n8 frags per warp (warp n-span = BN/4)
    constexpr int WIW = BN / 32;         // W float4 loads per thread

    __shared__ __nv_bfloat16 sA[2][2][BM * PK];   // [buf][hi/lo]
    __shared__ __nv_bfloat16 sB[2][2][BN * PK];

    const int tid  = threadIdx.x;
    const int lane = tid & 31;
    const int wid  = tid >> 5;     // 0..7
    const int wm   = wid & 1;      // 2 m-blocks of 32
    const int wn   = wid >> 1;     // 4 n-blocks of BN/4
    const int lr   = lane >> 2;
    const int lc   = lane & 3;
    const int bm   = blockIdx.y * BM;
    const int bn   = blockIdx.x * BN;

    const int t1   = K1 >> 5;
    const int tTot = t1 + (K2 >> 5);

    const int ldr  = tid >> 3;         // 0..31 row base
    const int ldc4 = (tid & 7) * 4;    // fp32 chunk offset in BK=32

    float4 av[2];
    float4 wv[WIW];

#define LDTILE(TT)                                                          \
    do {                                                                    \
        const float *A_, *W_; int lda_, K_, kt_;                            \
        if ((TT) < t1) { A_ = A1; W_ = W1; lda_ = lda1; K_ = K1; kt_ = (TT) << 5; } \
        else           { A_ = A2; W_ = W2; lda_ = lda2; K_ = K2; kt_ = ((TT) - t1) << 5; } \
        _Pragma("unroll")                                                   \
        for (int p = 0; p < 2; p++) {                                       \
            int r = ldr + p * 32;                                           \
            av[p] = *(const float4*)(A_ + (size_t)(bm + r) * lda_ + kt_ + ldc4); \
        }                                                                   \
        _Pragma("unroll")                                                   \
        for (int p = 0; p < WIW; p++) {                                     \
            int r = ldr + p * 32;                                           \
            wv[p] = *(const float4*)(W_ + (size_t)(bn + r) * K_ + kt_ + ldc4); \
        }                                                                   \
    } while (0)

#define STTILE(BUF)                                                         \
    do {                                                                    \
        _Pragma("unroll")                                                   \
        for (int p = 0; p < 2; p++) {                                       \
            int r = ldr + p * 32;                                           \
            uint2 H, L; split4(av[p], H, L);                                \
            *(uint2*)&sA[(BUF)][0][r * PK + ldc4] = H;                      \
            *(uint2*)&sA[(BUF)][1][r * PK + ldc4] = L;                      \
        }                                                                   \
        _Pragma("unroll")                                                   \
        for (int p = 0; p < WIW; p++) {                                     \
            int r = ldr + p * 32;                                           \
            uint2 H, L; split4(wv[p], H, L);                                \
            *(uint2*)&sB[(BUF)][0][r * PK + ldc4] = H;                      \
            *(uint2*)&sB[(BUF)][1][r * PK + ldc4] = L;                      \
        }                                                                   \
    } while (0)

    float D[2][WNJ][4];
    #pragma unroll
    for (int i = 0; i < 2; i++)
        #pragma unroll
        for (int j = 0; j < WNJ; j++)
            #pragma unroll
            for (int q = 0; q < 4; q++) D[i][j][q] = 0.0f;

    LDTILE(0);
    STTILE(0);
    __syncthreads();

    for (int tt = 0; tt < tTot; tt++) {
        const int buf = tt & 1;
        if (tt + 1 < tTot) LDTILE(tt + 1);

        #pragma unroll
        for (int k16 = 0; k16 < 2; k16++) {
            const int k0 = k16 * 16;
            unsigned Ah[2][4], Al[2][4];
            #pragma unroll
            for (int mi = 0; mi < 2; mi++) {
                int m0 = wm * 32 + mi * 16;
                const __nv_bfloat16* ph = &sA[buf][0][(m0 + lr) * PK + k0 + 2 * lc];
                const __nv_bfloat16* pl = &sA[buf][1][(m0 + lr) * PK + k0 + 2 * lc];
                Ah[mi][0] = *(const unsigned*)ph;
                Ah[mi][1] = *(const unsigned*)(ph + 8 * PK);
                Ah[mi][2] = *(const unsigned*)(ph + 8);
                Ah[mi][3] = *(const unsigned*)(ph + 8 * PK + 8);
                Al[mi][0] = *(const unsigned*)pl;
                Al[mi][1] = *(const unsigned*)(pl + 8 * PK);
                Al[mi][2] = *(const unsigned*)(pl + 8);
                Al[mi][3] = *(const unsigned*)(pl + 8 * PK + 8);
            }
            unsigned Bh[WNJ][2], Bl[WNJ][2];
            #pragma unroll
            for (int nj = 0; nj < WNJ; nj++) {
                int n0 = wn * (BN / 4) + nj * 8;
                const __nv_bfloat16* ph = &sB[buf][0][(n0 + lr) * PK + k0 + 2 * lc];
                const __nv_bfloat16* pl = &sB[buf][1][(n0 + lr) * PK + k0 + 2 * lc];
                Bh[nj][0] = *(const unsigned*)ph;
                Bh[nj][1] = *(const unsigned*)(ph + 8);
                Bl[nj][0] = *(const unsigned*)pl;
                Bl[nj][1] = *(const unsigned*)(pl + 8);
            }
            #pragma unroll
            for (int mi = 0; mi < 2; mi++)
                #pragma unroll
                for (int nj = 0; nj < WNJ; nj++) {
                    mma16816(D[mi][nj], Ah[mi], Bh[nj]);
                    mma16816(D[mi][nj], Ah[mi], Bl[nj]);
                    mma16816(D[mi][nj], Al[mi], Bh[nj]);
                }
        }

        if (tt + 1 < tTot) STTILE(buf ^ 1);
        __syncthreads();
    }

#undef LDTILE
#undef STTILE

    // epilogue
    #pragma unroll
    for (int mi = 0; mi < 2; mi++) {
        #pragma unroll
        for (int nj = 0; nj < WNJ; nj++) {
            int r = bm + wm * 32 + mi * 16 + lr;
            int c = bn + wn * (BN / 4) + nj * 8 + lc * 2;
            float2 bb = *(const float2*)&bias[c];
            float v0 = D[mi][nj][0] + bb.x;
            float v1 = D[mi][nj][1] + bb.y;
            float v2 = D[mi][nj][2] + bb.x;
            float v3 = D[mi][nj][3] + bb.y;
            if (RELU) {
                v0 = fmaxf(v0, 0.0f); v1 = fmaxf(v1, 0.0f);
                v2 = fmaxf(v2, 0.0f); v3 = fmaxf(v3, 0.0f);
            }
            *(float2*)(C + (size_t)r * ldc + c)       = make_float2(v0, v1);
            *(float2*)(C + (size_t)(r + 8) * ldc + c) = make_float2(v2, v3);
        }
    }
}

extern "C" void kernel_launch(void* const* d_in, const int* in_sizes, int n_in,
                              void* d_out, int out_size)
{
    const float* inputs = (const float*)d_in[0];   // [256,128,1024]
    const float* W_ih   = (const float*)d_in[1];   // [2048,1024]
    const float* b_ih   = (const float*)d_in[2];
    const float* W_hh   = (const float*)d_in[3];   // [2048,2048]
    const float* b_hh   = (const float*)d_in[4];
    const float* W_fc   = (const float*)d_in[5];   // [1024,2048]
    const float* b_fc   = (const float*)d_in[6];
    float* out = (float*)d_out;                    // [256,129,1024]

    float* h_base = nullptr; float* bias_cell = nullptr;
    cudaGetSymbolAddress((void**)&h_base, g_h);
    cudaGetSymbolAddress((void**)&bias_cell, g_bias_cell);
    float* h[2] = { h_base, h_base + (size_t)BATCH * HID };

    init_kernel<<<(BATCH * HID + 255) / 256, 256>>>(b_ih, b_hh);

    dim3 cellGrid(HID / 64, BATCH / 64);   // 32 x 4 = 128 CTAs
    dim3 fcGrid(FEAT / 32, BATCH / 64);    // 32 x 4 = 128 CTAs

    int cur = 0;
    for (int t = 0; t < NWARM; t++) {
        gemm_split<64, true><<<cellGrid, 256>>>(
            inputs + (size_t)t * FEAT, NWARM * FEAT, W_ih, FEAT,
            h[cur], HID, W_hh, HID,
            bias_cell, h[cur ^ 1], HID);
        cur ^= 1;
    }
    gemm_split<32, false><<<fcGrid, 256>>>(
        h[cur], HID, W_fc, HID,
        nullptr, 0, nullptr, 0,
        b_fc, out, LDOUT);
    for (int s = 1; s <= TSTEPS; s++) {
        gemm_split<64, true><<<cellGrid, 256>>>(
            out + (size_t)(s - 1) * FEAT, LDOUT, W_ih, FEAT,
            h[cur], HID, W_hh, HID,
            bias_cell, h[cur ^ 1], HID);
        cur ^= 1;
        gemm_split<32, false><<<fcGrid, 256>>>(
            h[cur], HID, W_fc, HID,
            nullptr, 0, nullptr, 0,
            b_fc, out + (size_t)s * FEAT, LDOUT);
    }
}

// round 7
// speedup vs baseline: 1.5994x; 1.5994x over previous
#include <cuda_runtime.h>
#include <cuda_bf16.h>
#include <stdint.h>

#define BATCH   256
#define NWARM   128
#define FEAT    1024
#define HID     2048
#define TSTEPS  128
#define OUT_T   (TSTEPS + 1)
#define LDOUT   (OUT_T * FEAT)

// Scratch: ping-pong hidden state + combined cell bias (allocation-free rule).
// NOTE: large __device__ weight statics crash the container — keep footprint small.
__device__ float g_h[2][BATCH * HID];
__device__ float g_bias_cell[HID];

__global__ void init_kernel(const float* __restrict__ b_ih,
                            const float* __restrict__ b_hh)
{
    int i = blockIdx.x * blockDim.x + threadIdx.x;
    if (i < HID) g_bias_cell[i] = b_ih[i] + b_hh[i];
    if (i < BATCH * HID) g_h[0][i] = 0.0f;
}

// Truncation split: hi = top-16-bits of fp32 (exact: f = hi + lo_exact),
// lo = rn_bf16(f - hi).
__device__ __forceinline__ void split4(float4 v, uint2& H, uint2& L) {
    unsigned bx = __float_as_uint(v.x), by = __float_as_uint(v.y);
    unsigned bz = __float_as_uint(v.z), bw = __float_as_uint(v.w);
    H.x = __byte_perm(bx, by, 0x7632);
    H.y = __byte_perm(bz, bw, 0x7632);
    float lx = v.x - __uint_as_float(bx & 0xFFFF0000u);
    float ly = v.y - __uint_as_float(by & 0xFFFF0000u);
    float lz = v.z - __uint_as_float(bz & 0xFFFF0000u);
    float lw = v.w - __uint_as_float(bw & 0xFFFF0000u);
    __nv_bfloat162 l0 = __floats2bfloat162_rn(lx, ly);
    __nv_bfloat162 l1 = __floats2bfloat162_rn(lz, lw);
    L.x = *(unsigned*)&l0;
    L.y = *(unsigned*)&l1;
}

__device__ __forceinline__ void mma16816(float d[4], const unsigned a[4], const unsigned b[2]) {
    asm volatile(
        "mma.sync.aligned.m16n8k16.row.col.f32.bf16.bf16.f32 "
        "{%0,%1,%2,%3}, {%4,%5,%6,%7}, {%8,%9}, {%0,%1,%2,%3};"
        : "+f"(d[0]), "+f"(d[1]), "+f"(d[2]), "+f"(d[3])
        : "r"(a[0]), "r"(a[1]), "r"(a[2]), "r"(a[3]), "r"(b[0]), "r"(b[1]));
}

__device__ __forceinline__ void ldsm4(unsigned r[4], unsigned addr) {
    asm volatile(
        "ldmatrix.sync.aligned.m8n8.x4.shared.b16 {%0,%1,%2,%3}, [%4];"
        : "=r"(r[0]), "=r"(r[1]), "=r"(r[2]), "=r"(r[3]) : "r"(addr));
}

// C[m,n] = act( sum_k A[m,k]*W[n,k] + bias[n] ), K split across 2 segments.
// A and W fp32 in gmem, split to bf16 (hi,lo) on the fly.
// D = Ah*Wh + Ah*Wl + Al*Wh  (fp32 accumulate in tensor cores).
// BM=64, BK=32; 256 threads = 8 warps, warp grid 2m x 2n x 2k:
// each warp owns a 32 x (BN/2) output tile for ONE k16-half of every BK tile;
// the two k-partials are reduced through smem at the end.
template<int BN, bool RELU>
__global__ __launch_bounds__(256)
void gemm_split(const float* __restrict__ A1, int lda1,
                const float* __restrict__ W1, int K1,
                const float* __restrict__ A2, int lda2,
                const float* __restrict__ W2, int K2,
                const float* __restrict__ bias,
                float* __restrict__ C, int ldc)
{
    constexpr int BM = 64, PK = 40;      // 80B pitch -> conflict-free ldmatrix phases
    constexpr int WNJ  = BN / 16;        // n8 frags per warp (warp n-span = BN/2)
    constexpr int WIW  = BN / 32;        // W float4 loads per thread
    constexpr int REGN = 2 * WNJ * 4;    // accumulator floats per thread

    constexpr int SA_ELE = 2 * 2 * BM * PK;     // [buf][hl][BM*PK]
    constexpr int SB_ELE = 2 * 2 * BN * PK;
    __shared__ __align__(16) __nv_bfloat16 smem_raw[SA_ELE + SB_ELE];
    __nv_bfloat16* sAb = smem_raw;
    __nv_bfloat16* sBb = smem_raw + SA_ELE;
    float* sRed = (float*)smem_raw;             // aliases dead tile buffers at the end

    const int tid  = threadIdx.x;
    const int lane = tid & 31;
    const int wid  = tid >> 5;     // 0..7
    const int wk   = wid & 1;          // k16-half
    const int wm   = (wid >> 1) & 1;   // 2 m-blocks of 32
    const int wn   = wid >> 2;         // 2 n-blocks of BN/2
    const int bm   = blockIdx.y * BM;
    const int bn   = blockIdx.x * BN;
    const int lr   = lane >> 2;
    const int lc   = lane & 3;
    const int k0   = wk * 16;

    const int t1   = K1 >> 5;
    const int tTot = t1 + (K2 >> 5);

    const int ldr  = tid >> 3;         // 0..31 row base for loaders
    const int ldc4 = (tid & 7) * 4;    // fp32 chunk offset in BK=32

    // ldmatrix per-lane element offsets (bf16 elements within an [row*PK+col] plane)
    const int offA = (wm * 32 + ((lane >> 3) & 1) * 8 + (lane & 7)) * PK
                   + k0 + (lane >> 4) * 8;
    const int offB = (wn * (BN / 2) + (lane >> 4) * 8 + (lane & 7)) * PK
                   + k0 + ((lane >> 3) & 1) * 8;

    const unsigned aBase = (unsigned)__cvta_generic_to_shared(sAb);
    const unsigned bBase = (unsigned)__cvta_generic_to_shared(sBb);

    float4 av[2];
    float4 wv[WIW];

#define LDTILE(TT)                                                          \
    do {                                                                    \
        const float *A_, *W_; int lda_, K_, kt_;                            \
        if ((TT) < t1) { A_ = A1; W_ = W1; lda_ = lda1; K_ = K1; kt_ = (TT) << 5; } \
        else           { A_ = A2; W_ = W2; lda_ = lda2; K_ = K2; kt_ = ((TT) - t1) << 5; } \
        _Pragma("unroll")                                                   \
        for (int p = 0; p < 2; p++) {                                       \
            int r = ldr + p * 32;                                           \
            av[p] = *(const float4*)(A_ + (size_t)(bm + r) * lda_ + kt_ + ldc4); \
        }                                                                   \
        _Pragma("unroll")                                                   \
        for (int p = 0; p < WIW; p++) {                                     \
            int r = ldr + p * 32;                                           \
            wv[p] = *(const float4*)(W_ + (size_t)(bn + r) * K_ + kt_ + ldc4); \
        }                                                                   \
    } while (0)

#define STTILE(BUF)                                                         \
    do {                                                                    \
        _Pragma("unroll")                                                   \
        for (int p = 0; p < 2; p++) {                                       \
            int r = ldr + p * 32;                                           \
            uint2 H, L; split4(av[p], H, L);                                \
            *(uint2*)&sAb[((BUF) * 2 + 0) * (BM * PK) + r * PK + ldc4] = H; \
            *(uint2*)&sAb[((BUF) * 2 + 1) * (BM * PK) + r * PK + ldc4] = L; \
        }                                                                   \
        _Pragma("unroll")                                                   \
        for (int p = 0; p < WIW; p++) {                                     \
            int r = ldr + p * 32;                                           \
            uint2 H, L; split4(wv[p], H, L);                                \
            *(uint2*)&sBb[((BUF) * 2 + 0) * (BN * PK) + r * PK + ldc4] = H; \
            *(uint2*)&sBb[((BUF) * 2 + 1) * (BN * PK) + r * PK + ldc4] = L; \
        }                                                                   \
    } while (0)

    float D[2][WNJ][4];
    #pragma unroll
    for (int i = 0; i < 2; i++)
        #pragma unroll
        for (int j = 0; j < WNJ; j++)
            #pragma unroll
            for (int q = 0; q < 4; q++) D[i][j][q] = 0.0f;

    LDTILE(0);
    STTILE(0);
    __syncthreads();

    for (int tt = 0; tt < tTot; tt++) {
        const int buf = tt & 1;
        if (tt + 1 < tTot) LDTILE(tt + 1);

        {
            const unsigned aHi = aBase + ((buf * 2 + 0) * (BM * PK) + offA) * 2;
            const unsigned aLo = aBase + ((buf * 2 + 1) * (BM * PK) + offA) * 2;
            const unsigned bHi = bBase + ((buf * 2 + 0) * (BN * PK) + offB) * 2;
            const unsigned bLo = bBase + ((buf * 2 + 1) * (BN * PK) + offB) * 2;

            unsigned Ah[2][4], Al[2][4];
            #pragma unroll
            for (int mi = 0; mi < 2; mi++) {
                ldsm4(Ah[mi], aHi + mi * (16 * PK * 2));
                ldsm4(Al[mi], aLo + mi * (16 * PK * 2));
            }
            unsigned Bh[WNJ][2], Bl[WNJ][2];
            #pragma unroll
            for (int p = 0; p < WNJ / 2; p++) {
                unsigned t4[4];
                ldsm4(t4, bHi + p * (16 * PK * 2));
                Bh[2 * p][0] = t4[0]; Bh[2 * p][1] = t4[1];
                Bh[2 * p + 1][0] = t4[2]; Bh[2 * p + 1][1] = t4[3];
                ldsm4(t4, bLo + p * (16 * PK * 2));
                Bl[2 * p][0] = t4[0]; Bl[2 * p][1] = t4[1];
                Bl[2 * p + 1][0] = t4[2]; Bl[2 * p + 1][1] = t4[3];
            }
            #pragma unroll
            for (int mi = 0; mi < 2; mi++)
                #pragma unroll
                for (int nj = 0; nj < WNJ; nj++) {
                    mma16816(D[mi][nj], Ah[mi], Bh[nj]);
                    mma16816(D[mi][nj], Ah[mi], Bl[nj]);
                    mma16816(D[mi][nj], Al[mi], Bh[nj]);
                }
        }

        if (tt + 1 < tTot) STTILE(buf ^ 1);
        __syncthreads();
    }

#undef LDTILE
#undef STTILE

    // ---- combine the two k16-partials through smem (tile buffers are dead) ----
    const int rebase = (wm * 2 + wn) * 32 + lane;   // 0..127, lane-contiguous
    if (wk == 1) {
        #pragma unroll
        for (int mi = 0; mi < 2; mi++)
            #pragma unroll
            for (int nj = 0; nj < WNJ; nj++)
                #pragma unroll
                for (int q = 0; q < 4; q++)
                    sRed[((mi * WNJ + nj) * 4 + q) * 128 + rebase] = D[mi][nj][q];
    }
    __syncthreads();
    if (wk == 0) {
        #pragma unroll
        for (int mi = 0; mi < 2; mi++)
            #pragma unroll
            for (int nj = 0; nj < WNJ; nj++)
                #pragma unroll
                for (int q = 0; q < 4; q++)
                    D[mi][nj][q] += sRed[((mi * WNJ + nj) * 4 + q) * 128 + rebase];

        // epilogue
        #pragma unroll
        for (int mi = 0; mi < 2; mi++) {
            #pragma unroll
            for (int nj = 0; nj < WNJ; nj++) {
                int r = bm + wm * 32 + mi * 16 + lr;
                int c = bn + wn * (BN / 2) + nj * 8 + lc * 2;
                float2 bb = *(const float2*)&bias[c];
                float v0 = D[mi][nj][0] + bb.x;
                float v1 = D[mi][nj][1] + bb.y;
                float v2 = D[mi][nj][2] + bb.x;
                float v3 = D[mi][nj][3] + bb.y;
                if (RELU) {
                    v0 = fmaxf(v0, 0.0f); v1 = fmaxf(v1, 0.0f);
                    v2 = fmaxf(v2, 0.0f); v3 = fmaxf(v3, 0.0f);
                }
                *(float2*)(C + (size_t)r * ldc + c)       = make_float2(v0, v1);
                *(float2*)(C + (size_t)(r + 8) * ldc + c) = make_float2(v2, v3);
            }
        }
    }
}

extern "C" void kernel_launch(void* const* d_in, const int* in_sizes, int n_in,
                              void* d_out, int out_size)
{
    const float* inputs = (const float*)d_in[0];   // [256,128,1024]
    const float* W_ih   = (const float*)d_in[1];   // [2048,1024]
    const float* b_ih   = (const float*)d_in[2];
    const float* W_hh   = (const float*)d_in[3];   // [2048,2048]
    const float* b_hh   = (const float*)d_in[4];
    const float* W_fc   = (const float*)d_in[5];   // [1024,2048]
    const float* b_fc   = (const float*)d_in[6];
    float* out = (float*)d_out;                    // [256,129,1024]

    float* h_base = nullptr; float* bias_cell = nullptr;
    cudaGetSymbolAddress((void**)&h_base, g_h);
    cudaGetSymbolAddress((void**)&bias_cell, g_bias_cell);
    float* h[2] = { h_base, h_base + (size_t)BATCH * HID };

    init_kernel<<<(BATCH * HID + 255) / 256, 256>>>(b_ih, b_hh);

    dim3 cellGrid(HID / 64, BATCH / 64);   // 32 x 4 = 128 CTAs
    dim3 fcGrid(FEAT / 32, BATCH / 64);    // 32 x 4 = 128 CTAs

    int cur = 0;
    for (int t = 0; t < NWARM; t++) {
        gemm_split<64, true><<<cellGrid, 256>>>(
            inputs + (size_t)t * FEAT, NWARM * FEAT, W_ih, FEAT,
            h[cur], HID, W_hh, HID,
            bias_cell, h[cur ^ 1], HID);
        cur ^= 1;
    }
    gemm_split<32, false><<<fcGrid, 256>>>(
        h[cur], HID, W_fc, HID,
        nullptr, 0, nullptr, 0,
        b_fc, out, LDOUT);
    for (int s = 1; s <= TSTEPS; s++) {
        gemm_split<64, true><<<cellGrid, 256>>>(
            out + (size_t)(s - 1) * FEAT, LDOUT, W_ih, FEAT,
            h[cur], HID, W_hh, HID,
            bias_cell, h[cur ^ 1], HID);
        cur ^= 1;
        gemm_split<32, false><<<fcGrid, 256>>>(
            h[cur], HID, W_fc, HID,
            nullptr, 0, nullptr, 0,
            b_fc, out + (size_t)s * FEAT, LDOUT);
    }
}

// round 10
// speedup vs baseline: 1.6100x; 1.0066x over previous
#include <cuda_runtime.h>
#include <cuda_bf16.h>
#include <stdint.h>

#define BATCH   256
#define NWARM   128
#define FEAT    1024
#define HID     2048
#define TSTEPS  128
#define OUT_T   (TSTEPS + 1)
#define LDOUT   (OUT_T * FEAT)

// Scratch (small statics only — large __device__ statics crash the container).
__device__ float g_h[2][BATCH * HID];
__device__ float g_bias_cell[HID];

__global__ void init_kernel(const float* __restrict__ b_ih,
                            const float* __restrict__ b_hh)
{
    int i = blockIdx.x * blockDim.x + threadIdx.x;
    if (i < HID) g_bias_cell[i] = b_ih[i] + b_hh[i];
    if (i < BATCH * HID) g_h[0][i] = 0.0f;
}

__device__ __forceinline__ uint32_t smem_u32(const void* p) {
    uint32_t a;
    asm("{ .reg .u64 t; cvta.to.shared.u64 t, %1; cvt.u32.u64 %0, t; }"
        : "=r"(a) : "l"(p));
    return a;
}

__device__ __forceinline__ void cp16(void* dst, const void* src) {
    asm volatile("cp.async.cg.shared.global [%0], [%1], 16;"
                 :: "r"(smem_u32(dst)), "l"(src));
}
#define CP_COMMIT() asm volatile("cp.async.commit_group;" ::: "memory")
#define CP_WAIT1()  asm volatile("cp.async.wait_group 1;" ::: "memory")

// hi = top 16 bits of fp32 (exact trunc), lo = rn_bf16(f - hi); packed pairs.
__device__ __forceinline__ unsigned hi_pack(float x, float y) {
    return __byte_perm(__float_as_uint(x), __float_as_uint(y), 0x7632);
}
__device__ __forceinline__ unsigned lo_pack(float x, float y) {
    float lx = x - __uint_as_float(__float_as_uint(x) & 0xFFFF0000u);
    float ly = y - __uint_as_float(__float_as_uint(y) & 0xFFFF0000u);
    __nv_bfloat162 p = __floats2bfloat162_rn(lx, ly);
    return *(unsigned*)&p;
}

__device__ __forceinline__ void mma16816(float d[4], const unsigned a[4], const unsigned b[2]) {
    asm volatile(
        "mma.sync.aligned.m16n8k16.row.col.f32.bf16.bf16.f32 "
        "{%0,%1,%2,%3}, {%4,%5,%6,%7}, {%8,%9}, {%0,%1,%2,%3};"
        : "+f"(d[0]), "+f"(d[1]), "+f"(d[2]), "+f"(d[3])
        : "r"(a[0]), "r"(a[1]), "r"(a[2]), "r"(a[3]), "r"(b[0]), "r"(b[1]));
}

// C[m,n] = act( sum_k A[m,k]*W[n,k] + bias[n] ), K over 2 segments.
// fp32 tiles staged via 2-deep cp.async ring in STATIC smem (<=48KB, no
// dynamic-smem opt-in). bf16 hi/lo split happens at fragment-read time
// (LDS.64 + PRMT/FSUB/CVT). D = Ah*Wh + Ah*Wl + Al*Wh in fp32 tensor accum.
// BM=64, BK=32; 256 threads, warp grid 2m x 2n x 2k, end smem k-reduction.
// PK=40 fp32 (160B rows): conflict-free for both STS.128 and LDS.64 phases.
template<int BN, bool RELU>
__global__ __launch_bounds__(256)
void gemm_cp(const float* __restrict__ A1, int lda1,
             const float* __restrict__ W1, int K1,
             const float* __restrict__ A2, int lda2,
             const float* __restrict__ W2, int K2,
             const float* __restrict__ bias,
             float* __restrict__ C, int ldc)
{
    constexpr int PK    = 40;                      // fp32 pitch; 160B = 10x16B
    constexpr int AFL   = 64 * PK;                 // A floats per stage
    constexpr int WFL   = BN * PK;
    constexpr int STGFL = AFL + WFL;               // stage floats
    constexpr int WNJ   = BN / 16;                 // n8 frags per warp (n-span BN/2)
    constexpr int WCH   = BN / 32;                 // W 16B-chunks per thread

    __shared__ __align__(16) float sm[2 * STGFL];  // 40KB (BN=64) static

    const int tid  = threadIdx.x;
    const int lane = tid & 31;
    const int wid  = tid >> 5;         // 0..7
    const int wk   = wid & 1;
    const int wm   = (wid >> 1) & 1;
    const int wn   = wid >> 2;
    const int bm   = blockIdx.y * 64;
    const int bn   = blockIdx.x * BN;
    const int lr   = lane >> 2;
    const int lc   = lane & 3;
    const int k0   = wk * 16;

    const int t1   = K1 >> 5;
    const int tTot = t1 + (K2 >> 5);

#define ISSUE(TT)                                                            \
    do {                                                                     \
        const float *A_, *W_; int lda_, K_, kt_;                             \
        if ((TT) < t1) { A_ = A1; W_ = W1; lda_ = lda1; K_ = K1; kt_ = (TT) << 5; } \
        else           { A_ = A2; W_ = W2; lda_ = lda2; K_ = K2; kt_ = ((TT) - t1) << 5; } \
        float* base = sm + ((TT) & 1) * STGFL;                               \
        _Pragma("unroll")                                                    \
        for (int p = 0; p < 2; p++) {                                        \
            int idx = tid + p * 256, r = idx >> 3, c = idx & 7;              \
            cp16(base + PK * r + 4 * c,                                      \
                 A_ + (size_t)(bm + r) * lda_ + kt_ + c * 4);                \
        }                                                                    \
        _Pragma("unroll")                                                    \
        for (int p = 0; p < WCH; p++) {                                      \
            int idx = tid + p * 256, r = idx >> 3, c = idx & 7;              \
            cp16(base + AFL + PK * r + 4 * c,                                \
                 W_ + (size_t)(bn + r) * K_ + kt_ + c * 4);                  \
        }                                                                    \
    } while (0)

    ISSUE(0); CP_COMMIT();
    ISSUE(1); CP_COMMIT();

    float D[2][WNJ][4];
    #pragma unroll
    for (int i = 0; i < 2; i++)
        #pragma unroll
        for (int j = 0; j < WNJ; j++)
            #pragma unroll
            for (int q = 0; q < 4; q++) D[i][j][q] = 0.0f;

    for (int t = 0; t < tTot; t++) {
        CP_WAIT1();                      // stage t landed (<=1 group pending)
        __syncthreads();

        const float* sA = sm + (t & 1) * STGFL;
        const float* sW = sA + AFL;

        unsigned Ah[2][4], Al[2][4];
        #pragma unroll
        for (int mi = 0; mi < 2; mi++) {
            const int m0 = wm * 32 + mi * 16;
            #pragma unroll
            for (int q = 0; q < 4; q++) {
                int row = m0 + lr + (q & 1) * 8;
                int k   = k0 + 2 * lc + (q >> 1) * 8;
                float2 f = *(const float2*)&sA[row * PK + k];
                Ah[mi][q] = hi_pack(f.x, f.y);
                Al[mi][q] = lo_pack(f.x, f.y);
            }
        }
        unsigned Bh[WNJ][2], Bl[WNJ][2];
        #pragma unroll
        for (int nj = 0; nj < WNJ; nj++) {
            const int n0 = wn * (BN / 2) + nj * 8;
            #pragma unroll
            for (int q = 0; q < 2; q++) {
                int k = k0 + 2 * lc + q * 8;
                float2 f = *(const float2*)&sW[(n0 + lr) * PK + k];
                Bh[nj][q] = hi_pack(f.x, f.y);
                Bl[nj][q] = lo_pack(f.x, f.y);
            }
        }
        #pragma unroll
        for (int mi = 0; mi < 2; mi++)
            #pragma unroll
            for (int nj = 0; nj < WNJ; nj++) {
                mma16816(D[mi][nj], Ah[mi], Bh[nj]);
                mma16816(D[mi][nj], Ah[mi], Bl[nj]);
                mma16816(D[mi][nj], Al[mi], Bh[nj]);
            }

        __syncthreads();                 // everyone done reading stage t
        if (t + 2 < tTot) ISSUE(t + 2);  // refill buffer (t&1)
        CP_COMMIT();
    }
#undef ISSUE

    // ---- combine the two k16-partials through smem (stage buffers dead) ----
    float* sRed = sm;
    const int rebase = (wm * 2 + wn) * 32 + lane;   // 0..127
    if (wk == 1) {
        #pragma unroll
        for (int mi = 0; mi < 2; mi++)
            #pragma unroll
            for (int nj = 0; nj < WNJ; nj++)
                #pragma unroll
                for (int q = 0; q < 4; q++)
                    sRed[((mi * WNJ + nj) * 4 + q) * 128 + rebase] = D[mi][nj][q];
    }
    __syncthreads();
    if (wk == 0) {
        #pragma unroll
        for (int mi = 0; mi < 2; mi++)
            #pragma unroll
            for (int nj = 0; nj < WNJ; nj++)
                #pragma unroll
                for (int q = 0; q < 4; q++)
                    D[mi][nj][q] += sRed[((mi * WNJ + nj) * 4 + q) * 128 + rebase];

        #pragma unroll
        for (int mi = 0; mi < 2; mi++) {
            #pragma unroll
            for (int nj = 0; nj < WNJ; nj++) {
                int r = bm + wm * 32 + mi * 16 + lr;
                int c = bn + wn * (BN / 2) + nj * 8 + lc * 2;
                float2 bb = *(const float2*)&bias[c];
                float v0 = D[mi][nj][0] + bb.x;
                float v1 = D[mi][nj][1] + bb.y;
                float v2 = D[mi][nj][2] + bb.x;
                float v3 = D[mi][nj][3] + bb.y;
                if (RELU) {
                    v0 = fmaxf(v0, 0.0f); v1 = fmaxf(v1, 0.0f);
                    v2 = fmaxf(v2, 0.0f); v3 = fmaxf(v3, 0.0f);
                }
                *(float2*)(C + (size_t)r * ldc + c)       = make_float2(v0, v1);
                *(float2*)(C + (size_t)(r + 8) * ldc + c) = make_float2(v2, v3);
            }
        }
    }
}

extern "C" void kernel_launch(void* const* d_in, const int* in_sizes, int n_in,
                              void* d_out, int out_size)
{
    const float* inputs = (const float*)d_in[0];   // [256,128,1024]
    const float* W_ih   = (const float*)d_in[1];   // [2048,1024]
    const float* b_ih   = (const float*)d_in[2];
    const float* W_hh   = (const float*)d_in[3];   // [2048,2048]
    const float* b_hh   = (const float*)d_in[4];
    const float* W_fc   = (const float*)d_in[5];   // [1024,2048]
    const float* b_fc   = (const float*)d_in[6];
    float* out = (float*)d_out;                    // [256,129,1024]

    float* h_base = nullptr; float* bias_cell = nullptr;
    cudaGetSymbolAddress((void**)&h_base, g_h);
    cudaGetSymbolAddress((void**)&bias_cell, g_bias_cell);
    float* h[2] = { h_base, h_base + (size_t)BATCH * HID };

    init_kernel<<<(BATCH * HID + 255) / 256, 256>>>(b_ih, b_hh);

    dim3 cellGrid(HID / 64, BATCH / 64);   // 32 x 4 = 128 CTAs
    dim3 fcGrid(FEAT / 32, BATCH / 64);    // 32 x 4 = 128 CTAs

    int cur = 0;
    for (int t = 0; t < NWARM; t++) {
        gemm_cp<64, true><<<cellGrid, 256>>>(
            inputs + (size_t)t * FEAT, NWARM * FEAT, W_ih, FEAT,
            h[cur], HID, W_hh, HID,
            bias_cell, h[cur ^ 1], HID);
        cur ^= 1;
    }
    gemm_cp<32, false><<<fcGrid, 256>>>(
        h[cur], HID, W_fc, HID,
        nullptr, 0, nullptr, 0,
        b_fc, out, LDOUT);
    for (int s = 1; s <= TSTEPS; s++) {
        gemm_cp<64, true><<<cellGrid, 256>>>(
            out + (size_t)(s - 1) * FEAT, LDOUT, W_ih, FEAT,
            h[cur], HID, W_hh, HID,
            bias_cell, h[cur ^ 1], HID);
        cur ^= 1;
        gemm_cp<32, false><<<fcGrid, 256>>>(
            h[cur], HID, W_fc, HID,
            nullptr, 0, nullptr, 0,
            b_fc, out + (size_t)s * FEAT, LDOUT);
    }
}

// round 12
// speedup vs baseline: 1.8408x; 1.1433x over previous
#include <cuda_runtime.h>
#include <cuda_bf16.h>
#include <stdint.h>

#define BATCH   256
#define NWARM   128
#define FEAT    1024
#define HID     2048
#define TSTEPS  128
#define OUT_T   (TSTEPS + 1)
#define LDOUT   (OUT_T * FEAT)

// Scratch (small statics only — large __device__ statics crash the container).
__device__ float g_h[2][BATCH * HID];
__device__ float g_part[2][BATCH * HID];   // K-split partials (4MB)
__device__ float g_bias_cell[HID];

__global__ void init_kernel(const float* __restrict__ b_ih,
                            const float* __restrict__ b_hh)
{
    int i = blockIdx.x * blockDim.x + threadIdx.x;
    if (i < HID) g_bias_cell[i] = b_ih[i] + b_hh[i];
    if (i < BATCH * HID) g_h[0][i] = 0.0f;
}

__device__ __forceinline__ uint32_t smem_u32(const void* p) {
    uint32_t a;
    asm("{ .reg .u64 t; cvta.to.shared.u64 t, %1; cvt.u32.u64 %0, t; }"
        : "=r"(a) : "l"(p));
    return a;
}

__device__ __forceinline__ void cp16(void* dst, const void* src) {
    asm volatile("cp.async.cg.shared.global [%0], [%1], 16;"
                 :: "r"(smem_u32(dst)), "l"(src));
}
#define CP_COMMIT() asm volatile("cp.async.commit_group;" ::: "memory")
#define CP_WAIT1()  asm volatile("cp.async.wait_group 1;" ::: "memory")

// hi = top 16 bits of fp32 (exact trunc), lo = rn_bf16(f - hi); packed pairs.
__device__ __forceinline__ unsigned hi_pack(float x, float y) {
    return __byte_perm(__float_as_uint(x), __float_as_uint(y), 0x7632);
}
__device__ __forceinline__ unsigned lo_pack(float x, float y) {
    float lx = x - __uint_as_float(__float_as_uint(x) & 0xFFFF0000u);
    float ly = y - __uint_as_float(__float_as_uint(y) & 0xFFFF0000u);
    __nv_bfloat162 p = __floats2bfloat162_rn(lx, ly);
    return *(unsigned*)&p;
}

__device__ __forceinline__ void mma16816(float d[4], const unsigned a[4], const unsigned b[2]) {
    asm volatile(
        "mma.sync.aligned.m16n8k16.row.col.f32.bf16.bf16.f32 "
        "{%0,%1,%2,%3}, {%4,%5,%6,%7}, {%8,%9}, {%0,%1,%2,%3};"
        : "+f"(d[0]), "+f"(d[1]), "+f"(d[2]), "+f"(d[3])
        : "r"(a[0]), "r"(a[1]), "r"(a[2]), "r"(a[3]), "r"(b[0]), "r"(b[1]));
}

// Partial GEMM: P[kk][m,n] = sum_{k in kk-half} A[m,k]*W[n,k], K over 2 segments.
// blockIdx.z = kk selects the K-half (tile range); partials reduced by
// reduce_kernel afterwards. fp32 tiles staged via 2-deep cp.async ring in
// static smem; bf16 hi/lo split at fragment-read time.
// D = Ah*Wh + Ah*Wl + Al*Wh. BM=64, BK=32; 256 thr, warps 2m x 2n x 2k.
template<int BN>
__global__ __launch_bounds__(256)
void gemm_cp(const float* __restrict__ A1, int lda1,
             const float* __restrict__ W1, int K1,
             const float* __restrict__ A2, int lda2,
             const float* __restrict__ W2, int K2,
             float* __restrict__ P, int pstride)
{
    constexpr int PK    = 40;                      // fp32 pitch; 160B = 10x16B
    constexpr int AFL   = 64 * PK;
    constexpr int WFL   = BN * PK;
    constexpr int STGFL = AFL + WFL;
    constexpr int WNJ   = BN / 16;
    constexpr int WCH   = BN / 32;

    __shared__ __align__(16) float sm[2 * STGFL];  // 40KB (BN=64) static

    const int tid  = threadIdx.x;
    const int lane = tid & 31;
    const int wid  = tid >> 5;
    const int wk   = wid & 1;
    const int wm   = (wid >> 1) & 1;
    const int wn   = wid >> 2;
    const int bm   = blockIdx.y * 64;
    const int bn   = blockIdx.x * BN;
    const int lr   = lane >> 2;
    const int lc   = lane & 3;
    const int k0   = wk * 16;

    const int t1   = K1 >> 5;
    const int tTot = t1 + (K2 >> 5);
    const int half = tTot >> 1;
    const int tBeg = blockIdx.z * half;
    const int tEnd = tBeg + half;

#define ISSUE(TT)                                                            \
    do {                                                                     \
        const float *A_, *W_; int lda_, K_, kt_;                             \
        if ((TT) < t1) { A_ = A1; W_ = W1; lda_ = lda1; K_ = K1; kt_ = (TT) << 5; } \
        else           { A_ = A2; W_ = W2; lda_ = lda2; K_ = K2; kt_ = ((TT) - t1) << 5; } \
        float* base = sm + ((TT) & 1) * STGFL;                               \
        _Pragma("unroll")                                                    \
        for (int p = 0; p < 2; p++) {                                        \
            int idx = tid + p * 256, r = idx >> 3, c = idx & 7;              \
            cp16(base + PK * r + 4 * c,                                      \
                 A_ + (size_t)(bm + r) * lda_ + kt_ + c * 4);                \
        }                                                                    \
        _Pragma("unroll")                                                    \
        for (int p = 0; p < WCH; p++) {                                      \
            int idx = tid + p * 256, r = idx >> 3, c = idx & 7;              \
            cp16(base + AFL + PK * r + 4 * c,                                \
                 W_ + (size_t)(bn + r) * K_ + kt_ + c * 4);                  \
        }                                                                    \
    } while (0)

    ISSUE(tBeg);     CP_COMMIT();
    ISSUE(tBeg + 1); CP_COMMIT();

    float D[2][WNJ][4];
    #pragma unroll
    for (int i = 0; i < 2; i++)
        #pragma unroll
        for (int j = 0; j < WNJ; j++)
            #pragma unroll
            for (int q = 0; q < 4; q++) D[i][j][q] = 0.0f;

    for (int t = tBeg; t < tEnd; t++) {
        CP_WAIT1();
        __syncthreads();

        const float* sA = sm + (t & 1) * STGFL;
        const float* sW = sA + AFL;

        unsigned Ah[2][4], Al[2][4];
        #pragma unroll
        for (int mi = 0; mi < 2; mi++) {
            const int m0 = wm * 32 + mi * 16;
            #pragma unroll
            for (int q = 0; q < 4; q++) {
                int row = m0 + lr + (q & 1) * 8;
                int k   = k0 + 2 * lc + (q >> 1) * 8;
                float2 f = *(const float2*)&sA[row * PK + k];
                Ah[mi][q] = hi_pack(f.x, f.y);
                Al[mi][q] = lo_pack(f.x, f.y);
            }
        }
        unsigned Bh[WNJ][2], Bl[WNJ][2];
        #pragma unroll
        for (int nj = 0; nj < WNJ; nj++) {
            const int n0 = wn * (BN / 2) + nj * 8;
            #pragma unroll
            for (int q = 0; q < 2; q++) {
                int k = k0 + 2 * lc + q * 8;
                float2 f = *(const float2*)&sW[(n0 + lr) * PK + k];
                Bh[nj][q] = hi_pack(f.x, f.y);
                Bl[nj][q] = lo_pack(f.x, f.y);
            }
        }
        #pragma unroll
        for (int mi = 0; mi < 2; mi++)
            #pragma unroll
            for (int nj = 0; nj < WNJ; nj++) {
                mma16816(D[mi][nj], Ah[mi], Bh[nj]);
                mma16816(D[mi][nj], Ah[mi], Bl[nj]);
                mma16816(D[mi][nj], Al[mi], Bh[nj]);
            }

        __syncthreads();
        if (t + 2 < tEnd) ISSUE(t + 2);
        CP_COMMIT();
    }
#undef ISSUE

    // ---- combine the two warp-level k16-partials through smem ----
    float* sRed = sm;
    const int rebase = (wm * 2 + wn) * 32 + lane;
    if (wk == 1) {
        #pragma unroll
        for (int mi = 0; mi < 2; mi++)
            #pragma unroll
            for (int nj = 0; nj < WNJ; nj++)
                #pragma unroll
                for (int q = 0; q < 4; q++)
                    sRed[((mi * WNJ + nj) * 4 + q) * 128 + rebase] = D[mi][nj][q];
    }
    __syncthreads();
    if (wk == 0) {
        float* Pk = P + (size_t)blockIdx.z * pstride;
        const int N = gridDim.x * BN;          // partial row stride
        #pragma unroll
        for (int mi = 0; mi < 2; mi++)
            #pragma unroll
            for (int nj = 0; nj < WNJ; nj++) {
                #pragma unroll
                for (int q = 0; q < 4; q++)
                    D[mi][nj][q] += sRed[((mi * WNJ + nj) * 4 + q) * 128 + rebase];
                int r = bm + wm * 32 + mi * 16 + lr;
                int c = bn + wn * (BN / 2) + nj * 8 + lc * 2;
                *(float2*)(Pk + (size_t)r * N + c) =
                    make_float2(D[mi][nj][0], D[mi][nj][1]);
                *(float2*)(Pk + (size_t)(r + 8) * N + c) =
                    make_float2(D[mi][nj][2], D[mi][nj][3]);
            }
    }
}

// out[r, c] = act(p0 + p1 + bias[c]); float4-vectorized.
template<bool RELU>
__global__ void reduce_kernel(const float4* __restrict__ p0,
                              const float4* __restrict__ p1,
                              const float* __restrict__ bias,
                              float* __restrict__ out,
                              int N4, int ldc, int total4)
{
    int i = blockIdx.x * blockDim.x + threadIdx.x;
    if (i >= total4) return;
    int row = i / N4, c4 = i % N4;
    float4 a = p0[i], b = p1[i];
    float4 bb = *(const float4*)&bias[c4 * 4];
    float4 v;
    v.x = a.x + b.x + bb.x;
    v.y = a.y + b.y + bb.y;
    v.z = a.z + b.z + bb.z;
    v.w = a.w + b.w + bb.w;
    if (RELU) {
        v.x = fmaxf(v.x, 0.0f); v.y = fmaxf(v.y, 0.0f);
        v.z = fmaxf(v.z, 0.0f); v.w = fmaxf(v.w, 0.0f);
    }
    *(float4*)(out + (size_t)row * ldc + c4 * 4) = v;
}

extern "C" void kernel_launch(void* const* d_in, const int* in_sizes, int n_in,
                              void* d_out, int out_size)
{
    const float* inputs = (const float*)d_in[0];   // [256,128,1024]
    const float* W_ih   = (const float*)d_in[1];   // [2048,1024]
    const float* b_ih   = (const float*)d_in[2];
    const float* W_hh   = (const float*)d_in[3];   // [2048,2048]
    const float* b_hh   = (const float*)d_in[4];
    const float* W_fc   = (const float*)d_in[5];   // [1024,2048]
    const float* b_fc   = (const float*)d_in[6];
    float* out = (float*)d_out;                    // [256,129,1024]

    float* h_base = nullptr; float* part = nullptr; float* bias_cell = nullptr;
    cudaGetSymbolAddress((void**)&h_base, g_h);
    cudaGetSymbolAddress((void**)&part, g_part);
    cudaGetSymbolAddress((void**)&bias_cell, g_bias_cell);
    float* h[2] = { h_base, h_base + (size_t)BATCH * HID };
    const int PSTRIDE = BATCH * HID;

    init_kernel<<<(BATCH * HID + 255) / 256, 256>>>(b_ih, b_hh);

    dim3 cellGrid(HID / 64, BATCH / 64, 2);   // 32 x 4 x 2 = 256 CTAs
    dim3 fcGrid(FEAT / 32, BATCH / 64, 2);    // 32 x 4 x 2 = 256 CTAs

    const int cellT4 = BATCH * HID / 4;       // 131072
    const int fcT4   = BATCH * FEAT / 4;      // 65536

    int cur = 0;
    for (int t = 0; t < NWARM; t++) {
        gemm_cp<64><<<cellGrid, 256>>>(
            inputs + (size_t)t * FEAT, NWARM * FEAT, W_ih, FEAT,
            h[cur], HID, W_hh, HID,
            part, PSTRIDE);
        reduce_kernel<true><<<(cellT4 + 255) / 256, 256>>>(
            (const float4*)part, (const float4*)(part + PSTRIDE),
            bias_cell, h[cur ^ 1], HID / 4, HID, cellT4);
        cur ^= 1;
    }
    gemm_cp<32><<<fcGrid, 256>>>(
        h[cur], HID, W_fc, HID,
        nullptr, 0, nullptr, 0,
        part, PSTRIDE);
    reduce_kernel<false><<<(fcT4 + 255) / 256, 256>>>(
        (const float4*)part, (const float4*)(part + PSTRIDE),
        b_fc, out, FEAT / 4, LDOUT, fcT4);
    for (int s = 1; s <= TSTEPS; s++) {
        gemm_cp<64><<<cellGrid, 256>>>(
            out + (size_t)(s - 1) * FEAT, LDOUT, W_ih, FEAT,
            h[cur], HID, W_hh, HID,
            part, PSTRIDE);
        reduce_kernel<true><<<(cellT4 + 255) / 256, 256>>>(
            (const float4*)part, (const float4*)(part + PSTRIDE),
            bias_cell, h[cur ^ 1], HID / 4, HID, cellT4);
        cur ^= 1;
        gemm_cp<32><<<fcGrid, 256>>>(
            h[cur], HID, W_fc, HID,
            nullptr, 0, nullptr, 0,
            part, PSTRIDE);
        reduce_kernel<false><<<(fcT4 + 255) / 256, 256>>>(
            (const float4*)part, (const float4*)(part + PSTRIDE),
            b_fc, out + (size_t)s * FEAT, FEAT / 4, LDOUT, fcT4);
    }
}

// round 13
// speedup vs baseline: 2.0787x; 1.1293x over previous
#include <cuda_runtime.h>
#include <cuda_bf16.h>
#include <stdint.h>

#define BATCH   256
#define NWARM   128
#define FEAT    1024
#define HID     2048
#define TSTEPS  128
#define OUT_T   (TSTEPS + 1)
#define LDOUT   (OUT_T * FEAT)

// Scratch (small statics only — large __device__ statics crash the container).
__device__ float g_h[2][BATCH * HID];
__device__ float g_part[2][BATCH * HID];   // K-split partials (4MB)
__device__ float g_bias_cell[HID];

__global__ void init_kernel(const float* __restrict__ b_ih,
                            const float* __restrict__ b_hh)
{
    int i = blockIdx.x * blockDim.x + threadIdx.x;
    if (i < HID) g_bias_cell[i] = b_ih[i] + b_hh[i];
    if (i < BATCH * HID) g_h[0][i] = 0.0f;
}

__device__ __forceinline__ uint32_t smem_u32(const void* p) {
    uint32_t a;
    asm("{ .reg .u64 t; cvta.to.shared.u64 t, %1; cvt.u32.u64 %0, t; }"
        : "=r"(a) : "l"(p));
    return a;
}

__device__ __forceinline__ void cp16(void* dst, const void* src) {
    asm volatile("cp.async.cg.shared.global [%0], [%1], 16;"
                 :: "r"(smem_u32(dst)), "l"(src));
}
#define CP_COMMIT() asm volatile("cp.async.commit_group;" ::: "memory")
#define CP_WAIT0()  asm volatile("cp.async.wait_group 0;" ::: "memory")

// hi = top 16 bits of fp32 (exact trunc), lo = rn_bf16(f - hi); packed pairs.
__device__ __forceinline__ unsigned hi_pack(float x, float y) {
    return __byte_perm(__float_as_uint(x), __float_as_uint(y), 0x7632);
}
__device__ __forceinline__ unsigned lo_pack(float x, float y) {
    float lx = x - __uint_as_float(__float_as_uint(x) & 0xFFFF0000u);
    float ly = y - __uint_as_float(__float_as_uint(y) & 0xFFFF0000u);
    __nv_bfloat162 p = __floats2bfloat162_rn(lx, ly);
    return *(unsigned*)&p;
}

__device__ __forceinline__ void mma16816(float d[4], const unsigned a[4], const unsigned b[2]) {
    asm volatile(
        "mma.sync.aligned.m16n8k16.row.col.f32.bf16.bf16.f32 "
        "{%0,%1,%2,%3}, {%4,%5,%6,%7}, {%8,%9}, {%0,%1,%2,%3};"
        : "+f"(d[0]), "+f"(d[1]), "+f"(d[2]), "+f"(d[3])
        : "r"(a[0]), "r"(a[1]), "r"(a[2]), "r"(a[3]), "r"(b[0]), "r"(b[1]));
}

__device__ __forceinline__ void ldsm4(unsigned r[4], unsigned addr) {
    asm volatile(
        "ldmatrix.sync.aligned.m8n8.x4.shared.b16 {%0,%1,%2,%3}, [%4];"
        : "=r"(r[0]), "=r"(r[1]), "=r"(r[2]), "=r"(r[3]) : "r"(addr));
}

// Partial GEMM: P[kk][m,n] = sum_{k in kk-half} A[m,k]*W[n,k], K over 2 segments.
// Per tile: (1) cp.async fp32 (XOR-8 swizzled, pitch 32) -> (2) one convert
// pass splits to bf16 hi/lo planes (pitch 40, R7-proven ldmatrix layout) ->
// (3) ldmatrix + 24 MMA/warp, zero ALU on the MMA path.
// D = Ah*Wh + Ah*Wl + Al*Wh. BM=64, BK=32; 256 thr, warps 2m x 2n x 2k.
template<int BN>
__global__ __launch_bounds__(256)
void gemm_cp(const float* __restrict__ A1, int lda1,
             const float* __restrict__ W1, int K1,
             const float* __restrict__ A2, int lda2,
             const float* __restrict__ W2, int K2,
             float* __restrict__ P, int pstride)
{
    constexpr int RT   = 64 + BN;              // fp32 rows (A then W)
    constexpr int PKB  = 40;                   // bf16 pitch (80B, ldmatrix-safe)
    constexpr int F32B = RT * 128;             // fp32 stage bytes (pitch 128B)
    constexpr int WNJ  = BN / 16;
    constexpr int WCH  = BN / 32;

    __shared__ __align__(16) char sm[F32B + RT * 80 * 2];
    char* F32 = sm;                            // [RT][32] fp32, chunk-swizzled
    char* AHI = sm + F32B;                     // [64][PKB] bf16
    char* ALO = AHI + 64 * 80;
    char* BHI = ALO + 64 * 80;
    char* BLO = BHI + BN * 80;

    const int tid  = threadIdx.x;
    const int lane = tid & 31;
    const int wid  = tid >> 5;
    const int wk   = wid & 1;
    const int wm   = (wid >> 1) & 1;
    const int wn   = wid >> 2;
    const int bm   = blockIdx.y * 64;
    const int bn   = blockIdx.x * BN;
    const int lr   = lane >> 2;
    const int lc   = lane & 3;
    const int k0   = wk * 16;

    const int t1   = K1 >> 5;
    const int tTot = t1 + (K2 >> 5);
    const int half = tTot >> 1;
    const int tBeg = blockIdx.z * half;
    const int tEnd = tBeg + half;

    // ldmatrix element offsets within a pitch-40 plane (R7-proven formulas)
    const int offA = (wm * 32 + ((lane >> 3) & 1) * 8 + (lane & 7)) * PKB
                   + k0 + (lane >> 4) * 8;
    const int offB = (wn * (BN / 2) + (lane >> 4) * 8 + (lane & 7)) * PKB
                   + k0 + ((lane >> 3) & 1) * 8;
    const unsigned aHi = smem_u32(AHI) + offA * 2;
    const unsigned aLo = smem_u32(ALO) + offA * 2;
    const unsigned bHi = smem_u32(BHI) + offB * 2;
    const unsigned bLo = smem_u32(BLO) + offB * 2;

#define ISSUE(TT)                                                            \
    do {                                                                     \
        const float *A_, *W_; int lda_, K_, kt_;                             \
        if ((TT) < t1) { A_ = A1; W_ = W1; lda_ = lda1; K_ = K1; kt_ = (TT) << 5; } \
        else           { A_ = A2; W_ = W2; lda_ = lda2; K_ = K2; kt_ = ((TT) - t1) << 5; } \
        _Pragma("unroll")                                                    \
        for (int p = 0; p < 2; p++) {                                        \
            int idx = tid + p * 256, r = idx >> 3, c = idx & 7;              \
            cp16(F32 + r * 128 + ((c ^ (r & 7)) << 4),                       \
                 A_ + (size_t)(bm + r) * lda_ + kt_ + c * 4);                \
        }                                                                    \
        _Pragma("unroll")                                                    \
        for (int p = 0; p < WCH; p++) {                                      \
            int idx = tid + p * 256, w = idx >> 3, c = idx & 7;              \
            cp16(F32 + (64 + w) * 128 + ((c ^ (w & 7)) << 4),                \
                 W_ + (size_t)(bn + w) * K_ + kt_ + c * 4);                  \
        }                                                                    \
    } while (0)

    ISSUE(tBeg); CP_COMMIT();

    float D[2][WNJ][4];
    #pragma unroll
    for (int i = 0; i < 2; i++)
        #pragma unroll
        for (int j = 0; j < WNJ; j++)
            #pragma unroll
            for (int q = 0; q < 4; q++) D[i][j][q] = 0.0f;

    for (int t = tBeg; t < tEnd; t++) {
        CP_WAIT0();
        __syncthreads();                        // fp32 tile visible everywhere

        // ---- convert: fp32 -> bf16 hi/lo planes (once per tile) ----
        #pragma unroll
        for (int i = tid; i < 2 * RT; i += 256) {
            int r = (i < RT) ? i : (i - RT);
            int h = (i < RT) ? 0 : 1;
            const char* src = F32 + r * 128;
            float4 f[4];
            #pragma unroll
            for (int j = 0; j < 4; j++)
                f[j] = *(const float4*)(src + (((4 * h + j) ^ (r & 7)) << 4));
            char* dH = (r < 64 ? AHI + r * 80 : BHI + (r - 64) * 80) + h * 32;
            char* dL = (r < 64 ? ALO + r * 80 : BLO + (r - 64) * 80) + h * 32;
            #pragma unroll
            for (int j2 = 0; j2 < 2; j2++) {
                uint4 H, L;
                H.x = hi_pack(f[2*j2].x,   f[2*j2].y);
                H.y = hi_pack(f[2*j2].z,   f[2*j2].w);
                H.z = hi_pack(f[2*j2+1].x, f[2*j2+1].y);
                H.w = hi_pack(f[2*j2+1].z, f[2*j2+1].w);
                L.x = lo_pack(f[2*j2].x,   f[2*j2].y);
                L.y = lo_pack(f[2*j2].z,   f[2*j2].w);
                L.z = lo_pack(f[2*j2+1].x, f[2*j2+1].y);
                L.w = lo_pack(f[2*j2+1].z, f[2*j2+1].w);
                *(uint4*)(dH + j2 * 16) = H;
                *(uint4*)(dL + j2 * 16) = L;
            }
        }
        __syncthreads();                        // bf16 ready; fp32 stage free

        if (t + 1 < tEnd) { ISSUE(t + 1); CP_COMMIT(); }

        // ---- MMA phase: ldmatrix + 24 MMAs, no ALU on the path ----
        unsigned Ah[2][4], Al[2][4];
        #pragma unroll
        for (int mi = 0; mi < 2; mi++) {
            ldsm4(Ah[mi], aHi + mi * (16 * PKB * 2));
            ldsm4(Al[mi], aLo + mi * (16 * PKB * 2));
        }
        unsigned Bh[WNJ][2], Bl[WNJ][2];
        #pragma unroll
        for (int p = 0; p < WNJ / 2; p++) {
            unsigned t4[4];
            ldsm4(t4, bHi + p * (16 * PKB * 2));
            Bh[2*p][0] = t4[0]; Bh[2*p][1] = t4[1];
            Bh[2*p+1][0] = t4[2]; Bh[2*p+1][1] = t4[3];
            ldsm4(t4, bLo + p * (16 * PKB * 2));
            Bl[2*p][0] = t4[0]; Bl[2*p][1] = t4[1];
            Bl[2*p+1][0] = t4[2]; Bl[2*p+1][1] = t4[3];
        }
        #pragma unroll
        for (int mi = 0; mi < 2; mi++)
            #pragma unroll
            for (int nj = 0; nj < WNJ; nj++) {
                mma16816(D[mi][nj], Ah[mi], Bh[nj]);
                mma16816(D[mi][nj], Ah[mi], Bl[nj]);
                mma16816(D[mi][nj], Al[mi], Bh[nj]);
            }
        __syncthreads();                        // frags consumed; planes reusable
    }
#undef ISSUE

    // ---- combine the two warp-level k16-partials through smem ----
    float* sRed = (float*)sm;                   // tile buffers dead
    const int rebase = (wm * 2 + wn) * 32 + lane;
    if (wk == 1) {
        #pragma unroll
        for (int mi = 0; mi < 2; mi++)
            #pragma unroll
            for (int nj = 0; nj < WNJ; nj++)
                #pragma unroll
                for (int q = 0; q < 4; q++)
                    sRed[((mi * WNJ + nj) * 4 + q) * 128 + rebase] = D[mi][nj][q];
    }
    __syncthreads();
    if (wk == 0) {
        float* Pk = P + (size_t)blockIdx.z * pstride;
        const int N = gridDim.x * BN;
        #pragma unroll
        for (int mi = 0; mi < 2; mi++)
            #pragma unroll
            for (int nj = 0; nj < WNJ; nj++) {
                #pragma unroll
                for (int q = 0; q < 4; q++)
                    D[mi][nj][q] += sRed[((mi * WNJ + nj) * 4 + q) * 128 + rebase];
                int r = bm + wm * 32 + mi * 16 + lr;
                int c = bn + wn * (BN / 2) + nj * 8 + lc * 2;
                *(float2*)(Pk + (size_t)r * N + c) =
                    make_float2(D[mi][nj][0], D[mi][nj][1]);
                *(float2*)(Pk + (size_t)(r + 8) * N + c) =
                    make_float2(D[mi][nj][2], D[mi][nj][3]);
            }
    }
}

// out[r, c] = act(p0 + p1 + bias[c]); float4-vectorized.
template<bool RELU>
__global__ void reduce_kernel(const float4* __restrict__ p0,
                              const float4* __restrict__ p1,
                              const float* __restrict__ bias,
                              float* __restrict__ out,
                              int N4, int ldc, int total4)
{
    int i = blockIdx.x * blockDim.x + threadIdx.x;
    if (i >= total4) return;
    int row = i / N4, c4 = i % N4;
    float4 a = p0[i], b = p1[i];
    float4 bb = *(const float4*)&bias[c4 * 4];
    float4 v;
    v.x = a.x + b.x + bb.x;
    v.y = a.y + b.y + bb.y;
    v.z = a.z + b.z + bb.z;
    v.w = a.w + b.w + bb.w;
    if (RELU) {
        v.x = fmaxf(v.x, 0.0f); v.y = fmaxf(v.y, 0.0f);
        v.z = fmaxf(v.z, 0.0f); v.w = fmaxf(v.w, 0.0f);
    }
    *(float4*)(out + (size_t)row * ldc + c4 * 4) = v;
}

extern "C" void kernel_launch(void* const* d_in, const int* in_sizes, int n_in,
                              void* d_out, int out_size)
{
    const float* inputs = (const float*)d_in[0];   // [256,128,1024]
    const float* W_ih   = (const float*)d_in[1];   // [2048,1024]
    const float* b_ih   = (const float*)d_in[2];
    const float* W_hh   = (const float*)d_in[3];   // [2048,2048]
    const float* b_hh   = (const float*)d_in[4];
    const float* W_fc   = (const float*)d_in[5];   // [1024,2048]
    const float* b_fc   = (const float*)d_in[6];
    float* out = (float*)d_out;                    // [256,129,1024]

    float* h_base = nullptr; float* part = nullptr; float* bias_cell = nullptr;
    cudaGetSymbolAddress((void**)&h_base, g_h);
    cudaGetSymbolAddress((void**)&part, g_part);
    cudaGetSymbolAddress((void**)&bias_cell, g_bias_cell);
    float* h[2] = { h_base, h_base + (size_t)BATCH * HID };
    const int PSTRIDE = BATCH * HID;

    init_kernel<<<(BATCH * HID + 255) / 256, 256>>>(b_ih, b_hh);

    dim3 cellGrid(HID / 64, BATCH / 64, 2);   // 32 x 4 x 2 = 256 CTAs
    dim3 fcGrid(FEAT / 32, BATCH / 64, 2);    // 32 x 4 x 2 = 256 CTAs

    const int cellT4 = BATCH * HID / 4;
    const int fcT4   = BATCH * FEAT / 4;

    int cur = 0;
    for (int t = 0; t < NWARM; t++) {
        gemm_cp<64><<<cellGrid, 256>>>(
            inputs + (size_t)t * FEAT, NWARM * FEAT, W_ih, FEAT,
            h[cur], HID, W_hh, HID,
            part, PSTRIDE);
        reduce_kernel<true><<<(cellT4 + 255) / 256, 256>>>(
            (const float4*)part, (const float4*)(part + PSTRIDE),
            bias_cell, h[cur ^ 1], HID / 4, HID, cellT4);
        cur ^= 1;
    }
    gemm_cp<32><<<fcGrid, 256>>>(
        h[cur], HID, W_fc, HID,
        nullptr, 0, nullptr, 0,
        part, PSTRIDE);
    reduce_kernel<false><<<(fcT4 + 255) / 256, 256>>>(
        (const float4*)part, (const float4*)(part + PSTRIDE),
        b_fc, out, FEAT / 4, LDOUT, fcT4);
    for (int s = 1; s <= TSTEPS; s++) {
        gemm_cp<64><<<cellGrid, 256>>>(
            out + (size_t)(s - 1) * FEAT, LDOUT, W_ih, FEAT,
            h[cur], HID, W_hh, HID,
            part, PSTRIDE);
        reduce_kernel<true><<<(cellT4 + 255) / 256, 256>>>(
            (const float4*)part, (const float4*)(part + PSTRIDE),
            bias_cell, h[cur ^ 1], HID / 4, HID, cellT4);
        cur ^= 1;
        gemm_cp<32><<<fcGrid, 256>>>(
            h[cur], HID, W_fc, HID,
            nullptr, 0, nullptr, 0,
            part, PSTRIDE);
        reduce_kernel<false><<<(fcT4 + 255) / 256, 256>>>(
            (const float4*)part, (const float4*)(part + PSTRIDE),
            b_fc, out + (size_t)s * FEAT, FEAT / 4, LDOUT, fcT4);
    }
}

// round 14
// speedup vs baseline: 2.2320x; 1.0737x over previous
#include <cuda_runtime.h>
#include <cuda_bf16.h>
#include <stdint.h>

#define BATCH   256
#define NWARM   128
#define FEAT    1024
#define HID     2048
#define TSTEPS  128
#define OUT_T   (TSTEPS + 1)
#define LDOUT   (OUT_T * FEAT)

// Scratch (small statics only — large __device__ statics crash the container).
__device__ float g_h[2][BATCH * HID];
__device__ float g_part[2][BATCH * HID];   // K-split partials (4MB)
__device__ float g_bias_cell[HID];

__global__ void init_kernel(const float* __restrict__ b_ih,
                            const float* __restrict__ b_hh)
{
    int i = blockIdx.x * blockDim.x + threadIdx.x;
    if (i < HID) g_bias_cell[i] = b_ih[i] + b_hh[i];
    if (i < BATCH * HID) g_h[0][i] = 0.0f;
}

__device__ __forceinline__ uint32_t smem_u32(const void* p) {
    uint32_t a;
    asm("{ .reg .u64 t; cvta.to.shared.u64 t, %1; cvt.u32.u64 %0, t; }"
        : "=r"(a) : "l"(p));
    return a;
}

// hi = top 16 bits of fp32 (exact trunc), lo = rn_bf16(f - hi); packed pairs.
__device__ __forceinline__ void split4(float4 v, uint2& H, uint2& L) {
    unsigned bx = __float_as_uint(v.x), by = __float_as_uint(v.y);
    unsigned bz = __float_as_uint(v.z), bw = __float_as_uint(v.w);
    H.x = __byte_perm(bx, by, 0x7632);
    H.y = __byte_perm(bz, bw, 0x7632);
    float lx = v.x - __uint_as_float(bx & 0xFFFF0000u);
    float ly = v.y - __uint_as_float(by & 0xFFFF0000u);
    float lz = v.z - __uint_as_float(bz & 0xFFFF0000u);
    float lw = v.w - __uint_as_float(bw & 0xFFFF0000u);
    __nv_bfloat162 l0 = __floats2bfloat162_rn(lx, ly);
    __nv_bfloat162 l1 = __floats2bfloat162_rn(lz, lw);
    L.x = *(unsigned*)&l0;
    L.y = *(unsigned*)&l1;
}

__device__ __forceinline__ void mma16816(float d[4], const unsigned a[4], const unsigned b[2]) {
    asm volatile(
        "mma.sync.aligned.m16n8k16.row.col.f32.bf16.bf16.f32 "
        "{%0,%1,%2,%3}, {%4,%5,%6,%7}, {%8,%9}, {%0,%1,%2,%3};"
        : "+f"(d[0]), "+f"(d[1]), "+f"(d[2]), "+f"(d[3])
        : "r"(a[0]), "r"(a[1]), "r"(a[2]), "r"(a[3]), "r"(b[0]), "r"(b[1]));
}

__device__ __forceinline__ void ldsm4(unsigned r[4], unsigned addr) {
    asm volatile(
        "ldmatrix.sync.aligned.m8n8.x4.shared.b16 {%0,%1,%2,%3}, [%4];"
        : "=r"(r[0]), "=r"(r[1]), "=r"(r[2]), "=r"(r[3]) : "r"(addr));
}

// Partial GEMM: P[kk][m,n] = sum_{k in kk-half} A[m,k]*W[n,k], K over 2 segments.
// Producer path: LDG fp32 -> register split -> STS bf16 hi/lo planes (no fp32
// smem round-trip). Double-buffered planes -> ONE __syncthreads per tile:
//   STS(t) ; sync ; LDG(t+1)->regs ; ldsm+MMA on buf[t&1]
// D = Ah*Wh + Ah*Wl + Al*Wh. BM=64, BK=32; 256 thr, warps 2m x 2n x 2k.
template<int BN>
__global__ __launch_bounds__(256)
void gemm_ks(const float* __restrict__ A1, int lda1,
             const float* __restrict__ W1, int K1,
             const float* __restrict__ A2, int lda2,
             const float* __restrict__ W2, int K2,
             float* __restrict__ P, int pstride)
{
    constexpr int PKB  = 40;                     // bf16 pitch (80B rows)
    constexpr int APB  = 64 * 80;                // A plane bytes
    constexpr int BPB  = BN * 80;                // B plane bytes
    constexpr int BUFB = 2 * APB + 2 * BPB;      // AHI|ALO|BHI|BLO
    constexpr int WNJ  = BN / 16;
    constexpr int WIW  = BN / 32;

    __shared__ __align__(16) char sm[2 * BUFB];  // 40KB (BN=64) static

    const int tid  = threadIdx.x;
    const int lane = tid & 31;
    const int wid  = tid >> 5;
    const int wk   = wid & 1;
    const int wm   = (wid >> 1) & 1;
    const int wn   = wid >> 2;
    const int bm   = blockIdx.y * 64;
    const int bn   = blockIdx.x * BN;
    const int lr   = lane >> 2;
    const int lc   = lane & 3;
    const int k0   = wk * 16;

    const int t1   = K1 >> 5;
    const int tTot = t1 + (K2 >> 5);
    const int half = tTot >> 1;
    const int tBeg = blockIdx.z * half;
    const int tEnd = tBeg + half;

    const int ldr  = tid >> 3;                   // 0..31
    const int ldc4 = (tid & 7) * 4;              // fp32 chunk in BK=32

    // ldmatrix byte offsets within a plane (R7/R13-proven formulas)
    const int offA = ((wm * 32 + ((lane >> 3) & 1) * 8 + (lane & 7)) * PKB
                      + k0 + (lane >> 4) * 8) * 2;
    const int offB = ((wn * (BN / 2) + (lane >> 4) * 8 + (lane & 7)) * PKB
                      + k0 + ((lane >> 3) & 1) * 8) * 2;
    const unsigned smBase = smem_u32(sm);

    float4 av[2];
    float4 wv[WIW];

#define LDTILE(TT)                                                           \
    do {                                                                     \
        const float *A_, *W_; int lda_, K_, kt_;                             \
        if ((TT) < t1) { A_ = A1; W_ = W1; lda_ = lda1; K_ = K1; kt_ = (TT) << 5; } \
        else           { A_ = A2; W_ = W2; lda_ = lda2; K_ = K2; kt_ = ((TT) - t1) << 5; } \
        _Pragma("unroll")                                                    \
        for (int p = 0; p < 2; p++)                                          \
            av[p] = *(const float4*)(A_ + (size_t)(bm + ldr + p * 32) * lda_ + kt_ + ldc4); \
        _Pragma("unroll")                                                    \
        for (int p = 0; p < WIW; p++)                                        \
            wv[p] = *(const float4*)(W_ + (size_t)(bn + ldr + p * 32) * K_ + kt_ + ldc4); \
    } while (0)

#define STTILE(BUF)                                                          \
    do {                                                                     \
        char* AHI_ = sm + (BUF) * BUFB;                                      \
        char* ALO_ = AHI_ + APB;                                             \
        char* BHI_ = ALO_ + APB;                                             \
        char* BLO_ = BHI_ + BPB;                                             \
        _Pragma("unroll")                                                    \
        for (int p = 0; p < 2; p++) {                                        \
            int r = ldr + p * 32;                                            \
            uint2 H, L; split4(av[p], H, L);                                 \
            *(uint2*)(AHI_ + r * 80 + ldc4 * 2) = H;                         \
            *(uint2*)(ALO_ + r * 80 + ldc4 * 2) = L;                         \
        }                                                                    \
        _Pragma("unroll")                                                    \
        for (int p = 0; p < WIW; p++) {                                      \
            int r = ldr + p * 32;                                            \
            uint2 H, L; split4(wv[p], H, L);                                 \
            *(uint2*)(BHI_ + r * 80 + ldc4 * 2) = H;                         \
            *(uint2*)(BLO_ + r * 80 + ldc4 * 2) = L;                         \
        }                                                                    \
    } while (0)

    float D[2][WNJ][4];
    #pragma unroll
    for (int i = 0; i < 2; i++)
        #pragma unroll
        for (int j = 0; j < WNJ; j++)
            #pragma unroll
            for (int q = 0; q < 4; q++) D[i][j][q] = 0.0f;

    LDTILE(tBeg);

    for (int t = tBeg; t < tEnd; t++) {
        const int buf = t & 1;
        STTILE(buf);
        __syncthreads();                         // the only sync per tile
        if (t + 1 < tEnd) LDTILE(t + 1);         // flight covers MMA phase

        const unsigned aHi = smBase + buf * BUFB + offA;
        const unsigned aLo = aHi + APB;
        const unsigned bHi = aLo + APB - offA + offB;
        const unsigned bLo = bHi + BPB;

        unsigned Ah[2][4], Al[2][4];
        #pragma unroll
        for (int mi = 0; mi < 2; mi++) {
            ldsm4(Ah[mi], aHi + mi * (16 * 80));
            ldsm4(Al[mi], aLo + mi * (16 * 80));
        }
        unsigned Bh[WNJ][2], Bl[WNJ][2];
        #pragma unroll
        for (int p = 0; p < WNJ / 2; p++) {
            unsigned t4[4];
            ldsm4(t4, bHi + p * (16 * 80));
            Bh[2*p][0] = t4[0]; Bh[2*p][1] = t4[1];
            Bh[2*p+1][0] = t4[2]; Bh[2*p+1][1] = t4[3];
            ldsm4(t4, bLo + p * (16 * 80));
            Bl[2*p][0] = t4[0]; Bl[2*p][1] = t4[1];
            Bl[2*p+1][0] = t4[2]; Bl[2*p+1][1] = t4[3];
        }
        #pragma unroll
        for (int mi = 0; mi < 2; mi++)
            #pragma unroll
            for (int nj = 0; nj < WNJ; nj++) {
                mma16816(D[mi][nj], Ah[mi], Bh[nj]);
                mma16816(D[mi][nj], Ah[mi], Bl[nj]);
                mma16816(D[mi][nj], Al[mi], Bh[nj]);
            }
    }
#undef LDTILE
#undef STTILE

    __syncthreads();                             // all ldsm done; smem reusable

    // ---- combine the two warp-level k16-partials through smem ----
    float* sRed = (float*)sm;
    const int rebase = (wm * 2 + wn) * 32 + lane;
    if (wk == 1) {
        #pragma unroll
        for (int mi = 0; mi < 2; mi++)
            #pragma unroll
            for (int nj = 0; nj < WNJ; nj++)
                #pragma unroll
                for (int q = 0; q < 4; q++)
                    sRed[((mi * WNJ + nj) * 4 + q) * 128 + rebase] = D[mi][nj][q];
    }
    __syncthreads();
    if (wk == 0) {
        float* Pk = P + (size_t)blockIdx.z * pstride;
        const int N = gridDim.x * BN;
        #pragma unroll
        for (int mi = 0; mi < 2; mi++)
            #pragma unroll
            for (int nj = 0; nj < WNJ; nj++) {
                #pragma unroll
                for (int q = 0; q < 4; q++)
                    D[mi][nj][q] += sRed[((mi * WNJ + nj) * 4 + q) * 128 + rebase];
                int r = bm + wm * 32 + mi * 16 + lr;
                int c = bn + wn * (BN / 2) + nj * 8 + lc * 2;
                *(float2*)(Pk + (size_t)r * N + c) =
                    make_float2(D[mi][nj][0], D[mi][nj][1]);
                *(float2*)(Pk + (size_t)(r + 8) * N + c) =
                    make_float2(D[mi][nj][2], D[mi][nj][3]);
            }
    }
}

// out[r, c] = act(p0 + p1 + bias[c]); float4-vectorized.
template<bool RELU>
__global__ void reduce_kernel(const float4* __restrict__ p0,
                              const float4* __restrict__ p1,
                              const float* __restrict__ bias,
                              float* __restrict__ out,
                              int N4, int ldc, int total4)
{
    int i = blockIdx.x * blockDim.x + threadIdx.x;
    if (i >= total4) return;
    int row = i / N4, c4 = i % N4;
    float4 a = p0[i], b = p1[i];
    float4 bb = *(const float4*)&bias[c4 * 4];
    float4 v;
    v.x = a.x + b.x + bb.x;
    v.y = a.y + b.y + bb.y;
    v.z = a.z + b.z + bb.z;
    v.w = a.w + b.w + bb.w;
    if (RELU) {
        v.x = fmaxf(v.x, 0.0f); v.y = fmaxf(v.y, 0.0f);
        v.z = fmaxf(v.z, 0.0f); v.w = fmaxf(v.w, 0.0f);
    }
    *(float4*)(out + (size_t)row * ldc + c4 * 4) = v;
}

extern "C" void kernel_launch(void* const* d_in, const int* in_sizes, int n_in,
                              void* d_out, int out_size)
{
    const float* inputs = (const float*)d_in[0];   // [256,128,1024]
    const float* W_ih   = (const float*)d_in[1];   // [2048,1024]
    const float* b_ih   = (const float*)d_in[2];
    const float* W_hh   = (const float*)d_in[3];   // [2048,2048]
    const float* b_hh   = (const float*)d_in[4];
    const float* W_fc   = (const float*)d_in[5];   // [1024,2048]
    const float* b_fc   = (const float*)d_in[6];
    float* out = (float*)d_out;                    // [256,129,1024]

    float* h_base = nullptr; float* part = nullptr; float* bias_cell = nullptr;
    cudaGetSymbolAddress((void**)&h_base, g_h);
    cudaGetSymbolAddress((void**)&part, g_part);
    cudaGetSymbolAddress((void**)&bias_cell, g_bias_cell);
    float* h[2] = { h_base, h_base + (size_t)BATCH * HID };
    const int PSTRIDE = BATCH * HID;

    init_kernel<<<(BATCH * HID + 255) / 256, 256>>>(b_ih, b_hh);

    dim3 cellGrid(HID / 64, BATCH / 64, 2);   // 32 x 4 x 2 = 256 CTAs
    dim3 fcGrid(FEAT / 32, BATCH / 64, 2);    // 32 x 4 x 2 = 256 CTAs

    const int cellT4 = BATCH * HID / 4;
    const int fcT4   = BATCH * FEAT / 4;

    int cur = 0;
    for (int t = 0; t < NWARM; t++) {
        gemm_ks<64><<<cellGrid, 256>>>(
            inputs + (size_t)t * FEAT, NWARM * FEAT, W_ih, FEAT,
            h[cur], HID, W_hh, HID,
            part, PSTRIDE);
        reduce_kernel<true><<<(cellT4 + 255) / 256, 256>>>(
            (const float4*)part, (const float4*)(part + PSTRIDE),
            bias_cell, h[cur ^ 1], HID / 4, HID, cellT4);
        cur ^= 1;
    }
    gemm_ks<32><<<fcGrid, 256>>>(
        h[cur], HID, W_fc, HID,
        nullptr, 0, nullptr, 0,
        part, PSTRIDE);
    reduce_kernel<false><<<(fcT4 + 255) / 256, 256>>>(
        (const float4*)part, (const float4*)(part + PSTRIDE),
        b_fc, out, FEAT / 4, LDOUT, fcT4);
    for (int s = 1; s <= TSTEPS; s++) {
        gemm_ks<64><<<cellGrid, 256>>>(
            out + (size_t)(s - 1) * FEAT, LDOUT, W_ih, FEAT,
            h[cur], HID, W_hh, HID,
            part, PSTRIDE);
        reduce_kernel<true><<<(cellT4 + 255) / 256, 256>>>(
            (const float4*)part, (const float4*)(part + PSTRIDE),
            bias_cell, h[cur ^ 1], HID / 4, HID, cellT4);
        cur ^= 1;
        gemm_ks<32><<<fcGrid, 256>>>(
            h[cur], HID, W_fc, HID,
            nullptr, 0, nullptr, 0,
            part, PSTRIDE);
        reduce_kernel<false><<<(fcT4 + 255) / 256, 256>>>(
            (const float4*)part, (const float4*)(part + PSTRIDE),
            b_fc, out + (size_t)s * FEAT, FEAT / 4, LDOUT, fcT4);
    }
}